// round 11
// baseline (speedup 1.0000x reference)
#include <cuda_runtime.h>
#include <cstdint>

#define ND 729
#define NA 180
#define NB 2
#define NH 512
#define NW 512
#define PI_D 3.141592653589793

// Scratch (no cudaMalloc allowed)
__device__ float2 g_filt2[NA * ND];    // batch-interleaved, PRE-SCALED by pi/180
__device__ float2 g_cs[NA];            // (cos*S, sin*S), S = 729/(2*pi)
__device__ float4 g_edge[NA];          // {f0_b0, f728_b0, f0_b1, f728_b1} (scaled)

// ---------------------------------------------------------------------------
// Kernel 1: filter via closed-form piecewise-linear conv kernel
//   h(d) = (1/729)*(1/8 + min(d,729-d)/1458),  output pre-scaled by pi/180.
// Prefix sums P,Q over the single row; doubled-array prefixes reconstructed.
// ---------------------------------------------------------------------------
__global__ void __launch_bounds__(256) k_filter(const float* __restrict__ sino) {
    __shared__ float  s_sh[768];
    __shared__ float2 pq[730];
    __shared__ float2 wsum[8];

    int tid = threadIdx.x, lane = tid & 31, wid = tid >> 5;
    int row = blockIdx.x;
    int b = (row >= NA) ? 1 : 0;
    int a = row - b * NA;
    const float* src = sino + row * ND;

    for (int i = tid; i < 768; i += 256) s_sh[i] = (i < ND) ? __ldg(src + i) : 0.f;
    __syncthreads();

    int j0 = tid * 3;
    float2 loc[3];
    float p = 0.f, q = 0.f;
    #pragma unroll
    for (int k = 0; k < 3; k++) {
        int j = j0 + k;
        float v = (j < 768) ? s_sh[j] : 0.f;
        p += v;
        q = fmaf((float)j, v, q);
        loc[k] = make_float2(p, q);
    }
    float tp = p, tq = q;

    #pragma unroll
    for (int o = 1; o < 32; o <<= 1) {
        float ax = __shfl_up_sync(0xffffffffu, p, o);
        float aq = __shfl_up_sync(0xffffffffu, q, o);
        if (lane >= o) { p += ax; q += aq; }
    }
    if (lane == 31) wsum[wid] = make_float2(p, q);
    __syncthreads();

    float wx = 0.f, wq = 0.f;
    #pragma unroll
    for (int w = 0; w < 8; w++)
        if (w < wid) { wx += wsum[w].x; wq += wsum[w].y; }
    float ex = wx + p - tp, eq = wq + q - tq;

    if (tid == 0) pq[0] = make_float2(0.f, 0.f);
    #pragma unroll
    for (int k = 0; k < 3; k++) {
        int j = j0 + k;
        if (j < ND) pq[j + 1] = make_float2(ex + loc[k].x, eq + loc[k].y);
    }
    __syncthreads();

    float T = pq[ND].x, Q9 = pq[ND].y;
    const float sc  = (float)(PI_D / (double)NA);
    const float c0T = T * sc * (1.0f / 5832.0f);
    const float c1  = sc * (1.0f / 1062882.0f);

    float* fdst = (float*)g_filt2;
    for (int n = tid; n < ND; n += 256) {
        float2 A = pq[n + 1];
        float2 B;
        if (n + 365 <= ND) B = pq[n + 365];
        else { float2 r = pq[n + 365 - ND]; B = make_float2(T + r.x, Q9 + r.y + 729.f * r.x); }
        float2 C;
        { float2 r = pq[n + 1]; C = make_float2(T + r.x, Q9 + r.y + 729.f * r.x); }
        float W = (float)(n + 729) * (C.x - B.x) - (C.y - B.y)
                + (B.y - A.y) - (float)n * (B.x - A.x);
        float f = fmaf(c1, W, c0T);
        fdst[(a * ND + n) * 2 + b] = f;
        if (n == 0)   ((float*)(g_edge + a))[2 * b + 0] = f;
        if (n == 728) ((float*)(g_edge + a))[2 * b + 1] = f;
    }

    if (tid == 0 && b == 0) {
        double ang = (double)a * (PI_D / 179.0);
        double S = 729.0 / (2.0 * PI_D);
        g_cs[a] = make_float2((float)(cos(ang) * S), (float)(sin(ang) * S));
    }
}

// ---------------------------------------------------------------------------
// Kernel 2: fused backprojection. Per pixel, t(a) = rS*cos(theta_a - phi):
//   - sign flips once over the grid  -> 8-step binary search (exact split)
//   - t unimodal on the positive run -> peak by bisection
//   - cap {t>=728} contiguous around peak -> two more searches
// total = prefix(f728 over cap) + prefix(f0 over negatives)
//       + gather loop over pos\cap (the true strip, ~2.5 angles avg).
// Scale already folded into f; finish with ReLU.
// ---------------------------------------------------------------------------
#define T_AT(a) ({ float2 c_ = cs[a]; fmaf(yc, c_.y, xc * c_.x); })

__global__ void __launch_bounds__(256) k_bp(float* __restrict__ out) {
    __shared__ float2 cs[NA];
    __shared__ float4 pre[NA + 1];

    int tid = threadIdx.x;
    for (int i = tid; i < NA; i += 256) cs[i] = g_cs[i];
    if (tid < 32) {
        float4 acc = make_float4(0.f, 0.f, 0.f, 0.f);
        float4 loc[6];
        #pragma unroll
        for (int k = 0; k < 6; k++) {
            int a2 = tid * 6 + k;
            float4 v = (a2 < NA) ? __ldg(g_edge + a2) : make_float4(0.f, 0.f, 0.f, 0.f);
            acc.x += v.x; acc.y += v.y; acc.z += v.z; acc.w += v.w;
            loc[k] = acc;
        }
        float4 tot = acc;
        #pragma unroll
        for (int o = 1; o < 32; o <<= 1) {
            float ax = __shfl_up_sync(0xffffffffu, acc.x, o);
            float ay = __shfl_up_sync(0xffffffffu, acc.y, o);
            float az = __shfl_up_sync(0xffffffffu, acc.z, o);
            float aw = __shfl_up_sync(0xffffffffu, acc.w, o);
            if (tid >= o) { acc.x += ax; acc.y += ay; acc.z += az; acc.w += aw; }
        }
        float4 excl = make_float4(acc.x - tot.x, acc.y - tot.y, acc.z - tot.z, acc.w - tot.w);
        #pragma unroll
        for (int k = 0; k < 6; k++) {
            int a2 = tid * 6 + k;
            if (a2 < NA)
                pre[a2 + 1] = make_float4(excl.x + loc[k].x, excl.y + loc[k].y,
                                          excl.z + loc[k].z, excl.w + loc[k].w);
        }
        if (tid == 0) pre[0] = make_float4(0.f, 0.f, 0.f, 0.f);
    }
    __syncthreads();

    // 8x4 lane tile, 2x4 warp tiles -> 16x16 block tile (minimize r/phi spread)
    int lane = tid & 31, w = tid >> 5;
    int x = ((int)blockIdx.x & 31) * 16 + (w & 1) * 8 + (lane & 7);
    int y = ((int)blockIdx.x >> 5) * 16 + (w >> 1) * 4 + (lane >> 3);
    float xc = (float)x - 256.0f;
    float yc = (float)y - 256.0f;

    // 1) exact sign-flip search: hi = first index with sign != s0 (sentinel NA)
    bool s0 = T_AT(0) > 0.f;
    int lo = 0, hi = NA;
    #pragma unroll
    for (int it = 0; it < 8; it++) {
        int mid = (lo + hi) >> 1;
        bool sm = (mid < NA) ? (T_AT(mid) > 0.f) : !s0;
        if (sm == s0) lo = mid; else hi = mid;
    }
    int p0, p1;
    if (s0) { p0 = 0; p1 = hi - 1; } else { p0 = hi; p1 = NA - 1; }

    float e0 = 0.f, e1 = 0.f;
    if (p0 <= p1) {
        // 2) peak of unimodal t on [p0, p1]
        int alo = p0, ahi = p1;
        #pragma unroll
        for (int it = 0; it < 8; it++) {
            if (alo < ahi) {
                int mid = (alo + ahi) >> 1;
                if (T_AT(mid) < T_AT(mid + 1)) alo = mid + 1; else ahi = mid;
            }
        }
        int peak = alo;

        int c0, c1;
        if (T_AT(peak) >= 728.f) {
            // 3a) first a in [p0, peak] with t >= 728 (t increasing)
            int l2 = p0, h2 = peak;
            #pragma unroll
            for (int it = 0; it < 8; it++) {
                if (l2 < h2) {
                    int mid = (l2 + h2) >> 1;
                    if (T_AT(mid) >= 728.f) h2 = mid; else l2 = mid + 1;
                }
            }
            c0 = h2;
            // 3b) last a in [peak, p1] with t >= 728 (t decreasing)
            l2 = peak; h2 = p1;
            #pragma unroll
            for (int it = 0; it < 8; it++) {
                if (l2 < h2) {
                    int mid = (l2 + h2 + 1) >> 1;
                    if (T_AT(mid) >= 728.f) l2 = mid; else h2 = mid - 1;
                }
            }
            c1 = l2;
            float4 Ha = pre[c1 + 1], La = pre[c0];
            e0 += Ha.y - La.y;
            e1 += Ha.w - La.w;
        } else {
            c0 = p1 + 1;   // empty cap: single loop covers [p0, p1]
            c1 = p1;
        }

        // 4) gather loops over pos \ cap (true strip)
        const float2* f2 = (const float2*)g_filt2;
        for (int a = p0; a < c0; a++) {
            float t = T_AT(a);
            t = fminf(fmaxf(t, 0.f), 728.f);
            float2 v = __ldg(f2 + a * ND + (int)t);
            e0 += v.x; e1 += v.y;
        }
        for (int a = c1 + 1; a <= p1; a++) {
            float t = T_AT(a);
            t = fminf(fmaxf(t, 0.f), 728.f);
            float2 v = __ldg(f2 + a * ND + (int)t);
            e0 += v.x; e1 += v.y;
        }
    }

    // 5) negative region -> f[a,0] via prefix (complement of [p0,p1])
    float4 Pe = pre[NA];
    if (p0 <= p1) {
        float4 A = pre[p0], B = pre[p1 + 1];
        e0 += A.x + (Pe.x - B.x);
        e1 += A.z + (Pe.z - B.z);
    } else {
        e0 += Pe.x;
        e1 += Pe.z;
    }

    int p = y * NW + x;
    out[p] = fmaxf(e0, 0.f);
    out[NH * NW + p] = fmaxf(e1, 0.f);
}

// ---------------------------------------------------------------------------
extern "C" void kernel_launch(void* const* d_in, const int* in_sizes, int n_in,
                              void* d_out, int out_size) {
    const float* sino = (const float*)d_in[0];
    float* out = (float*)d_out;

    k_filter<<<NB * NA, 256>>>(sino);
    k_bp<<<1024, 256>>>(out);
}

// round 12
// speedup vs baseline: 2.4056x; 2.4056x over previous
#include <cuda_runtime.h>
#include <cstdint>

#define ND 729
#define NA 180
#define NB 2
#define NH 512
#define NW 512
#define PI_D 3.141592653589793

// Scratch (no cudaMalloc allowed)
__device__ float2 g_filt2[NA * ND];    // batch-interleaved, PRE-SCALED by pi/180
__device__ float2 g_cs[NA];            // (cos*S, sin*S), S = 729/(2*pi)
__device__ float4 g_edge[NA];          // {f0_b0, f728_b0, f0_b1, f728_b1} (scaled)
__device__ float2 g_corr[NH * NW];     // strip corrections (b0, b1)

// ---------------------------------------------------------------------------
// Kernel 1: filter via closed-form piecewise-linear conv kernel
//   h(d) = (1/729)*(1/8 + min(d,729-d)/1458), output pre-scaled by pi/180.
// Prefix sums P,Q over the single row; doubled-array prefixes reconstructed:
//   j<=729: P2=P[j], Q2=Q[j];  j>729: P2=T+P[j-729], Q2=Q729+Q[j-729]+729*P[j-729]
// Also zeroes g_corr (ordering: strip launches after filter completes).
// ---------------------------------------------------------------------------
__global__ void __launch_bounds__(256) k_filter(const float* __restrict__ sino) {
    __shared__ float  s_sh[768];
    __shared__ float2 pq[730];
    __shared__ float2 wsum[8];

    int tid = threadIdx.x, lane = tid & 31, wid = tid >> 5;
    int row = blockIdx.x;
    int b = (row >= NA) ? 1 : 0;
    int a = row - b * NA;
    const float* src = sino + row * ND;

    // zero my slice of g_corr (729 float2s per block)
    {
        int per = (NH * NW + NB * NA - 1) / (NB * NA);     // 729
        int base = row * per;
        for (int i = tid; i < per; i += 256) {
            int j = base + i;
            if (j < NH * NW) g_corr[j] = make_float2(0.f, 0.f);
        }
    }

    for (int i = tid; i < 768; i += 256) s_sh[i] = (i < ND) ? __ldg(src + i) : 0.f;
    __syncthreads();

    int j0 = tid * 3;
    float2 loc[3];
    float p = 0.f, q = 0.f;
    #pragma unroll
    for (int k = 0; k < 3; k++) {
        int j = j0 + k;
        float v = (j < 768) ? s_sh[j] : 0.f;
        p += v;
        q = fmaf((float)j, v, q);
        loc[k] = make_float2(p, q);
    }
    float tp = p, tq = q;

    #pragma unroll
    for (int o = 1; o < 32; o <<= 1) {
        float ax = __shfl_up_sync(0xffffffffu, p, o);
        float aq = __shfl_up_sync(0xffffffffu, q, o);
        if (lane >= o) { p += ax; q += aq; }
    }
    if (lane == 31) wsum[wid] = make_float2(p, q);
    __syncthreads();

    float wx = 0.f, wq = 0.f;
    #pragma unroll
    for (int w = 0; w < 8; w++)
        if (w < wid) { wx += wsum[w].x; wq += wsum[w].y; }
    float ex = wx + p - tp, eq = wq + q - tq;

    if (tid == 0) pq[0] = make_float2(0.f, 0.f);
    #pragma unroll
    for (int k = 0; k < 3; k++) {
        int j = j0 + k;
        if (j < ND) pq[j + 1] = make_float2(ex + loc[k].x, eq + loc[k].y);
    }
    __syncthreads();

    float T = pq[ND].x, Q9 = pq[ND].y;
    const float sc  = (float)(PI_D / (double)NA);
    const float c0T = T * sc * (1.0f / 5832.0f);
    const float c1  = sc * (1.0f / 1062882.0f);

    float* fdst = (float*)g_filt2;
    for (int n = tid; n < ND; n += 256) {
        float2 A = pq[n + 1];
        float2 B;
        if (n + 365 <= ND) B = pq[n + 365];
        else { float2 r = pq[n + 365 - ND]; B = make_float2(T + r.x, Q9 + r.y + 729.f * r.x); }
        float2 C;
        { float2 r = pq[n + 1]; C = make_float2(T + r.x, Q9 + r.y + 729.f * r.x); }
        float W = (float)(n + 729) * (C.x - B.x) - (C.y - B.y)
                + (B.y - A.y) - (float)n * (B.x - A.x);
        float f = fmaf(c1, W, c0T);
        fdst[(a * ND + n) * 2 + b] = f;
        if (n == 0)   ((float*)(g_edge + a))[2 * b + 0] = f;
        if (n == 728) ((float*)(g_edge + a))[2 * b + 1] = f;
    }

    if (tid == 0 && b == 0) {
        double ang = (double)a * (PI_D / 179.0);
        double S = 729.0 / (2.0 * PI_D);
        g_cs[a] = make_float2((float)(cos(ang) * S), (float)(sin(ang) * S));
    }
}

// ---------------------------------------------------------------------------
// Kernel 2: strip pass (angle-major scatter) into g_corr. For each angle only
// the band 0 < t < 728 (<= 8.9 pixels wide along the minor axis) needs
//   corr = f[a,idx] - f[a,728]   (t>0 inside the band, matching base's sign)
// Warp = (angle, 32-chunk of major axis): lanes at equal band depth read
// nearly the same f element (L1 broadcast).
// ---------------------------------------------------------------------------
__global__ void __launch_bounds__(256) k_strip() {
    int w = threadIdx.x >> 5, lane = threadIdx.x & 31;
    int g = blockIdx.x * 8 + w;           // 0..2879
    int a = g >> 4;
    int m = (g & 15) * 32 + lane;         // major coord 0..511

    float2 c2 = __ldg(&g_cs[a]);
    float4 e  = __ldg(&g_edge[a]);
    float cx = c2.x, cy = c2.y;
    bool ymin = fabsf(cy) >= fabsf(cx);   // minor axis = y if true
    float A = ymin ? cx : cy;             // major coeff
    float Bc = ymin ? cy : cx;            // minor coeff, |Bc| >= 82
    float mc = (float)m - 256.f;
    float tA = mc * A;
    float r0 = (0.f - tA) / Bc;
    float r1 = (728.f - tA) / Bc;
    int mn0 = (int)floorf(fminf(r0, r1)) + 256 - 1;
    int CNT = (int)(728.f / fabsf(Bc)) + 3;

    const float2* frow = (const float2*)g_filt2 + a * ND;
    for (int k = 0; k < CNT; k++) {
        int mn = mn0 + k;
        if ((unsigned)mn < (unsigned)NW) {
            float mnc = (float)mn - 256.f;
            float xcv = ymin ? mc : mnc;
            float ycv = ymin ? mnc : mc;
            float t = fmaf(ycv, cy, xcv * cx);   // identical expr to k_base
            if (t > 0.f && t < 728.f) {
                int idx = (int)t;
                float2 v = __ldg(frow + idx);
                int x = ymin ? m : mn;
                int y = ymin ? mn : m;
                float* cp = (float*)(g_corr + y * NW + x);
                atomicAdd(cp + 0, v.x - e.y);
                atomicAdd(cp + 1, v.y - e.w);
            }
        }
    }
}

// ---------------------------------------------------------------------------
// Kernel 3 (last): base sums + corr + ReLU -> out.
// base = sum_a (t(a)>0 ? f[a,728] : f[a,0]) via exact single-flip binary
// search (8 steps, same fma predicate as strip) + 4-channel prefix lookups.
// ---------------------------------------------------------------------------
__global__ void __launch_bounds__(256) k_base(float* __restrict__ out) {
    __shared__ float2 cs[NA];
    __shared__ float4 pre[NA + 1];
    int tid = threadIdx.x;
    for (int i = tid; i < NA; i += 256) cs[i] = g_cs[i];
    if (tid < 32) {
        float4 acc = make_float4(0.f, 0.f, 0.f, 0.f);
        float4 loc[6];
        #pragma unroll
        for (int k = 0; k < 6; k++) {
            int a2 = tid * 6 + k;
            float4 v = (a2 < NA) ? __ldg(g_edge + a2) : make_float4(0.f, 0.f, 0.f, 0.f);
            acc.x += v.x; acc.y += v.y; acc.z += v.z; acc.w += v.w;
            loc[k] = acc;
        }
        float4 tot = acc;
        #pragma unroll
        for (int o = 1; o < 32; o <<= 1) {
            float ax = __shfl_up_sync(0xffffffffu, acc.x, o);
            float ay = __shfl_up_sync(0xffffffffu, acc.y, o);
            float az = __shfl_up_sync(0xffffffffu, acc.z, o);
            float aw = __shfl_up_sync(0xffffffffu, acc.w, o);
            if (tid >= o) { acc.x += ax; acc.y += ay; acc.z += az; acc.w += aw; }
        }
        float4 excl = make_float4(acc.x - tot.x, acc.y - tot.y, acc.z - tot.z, acc.w - tot.w);
        #pragma unroll
        for (int k = 0; k < 6; k++) {
            int a2 = tid * 6 + k;
            if (a2 < NA)
                pre[a2 + 1] = make_float4(excl.x + loc[k].x, excl.y + loc[k].y,
                                          excl.z + loc[k].z, excl.w + loc[k].w);
        }
        if (tid == 0) pre[0] = make_float4(0.f, 0.f, 0.f, 0.f);
    }
    __syncthreads();

    int gid = blockIdx.x * 256 + tid;     // 0..262143
    int x = gid & (NW - 1);
    int y = gid >> 9;
    float xc = (float)x - 256.0f;
    float yc = (float)y - 256.0f;

    bool s0 = fmaf(yc, cs[0].y, xc * cs[0].x) > 0.f;
    int lo = 0, hi = NA;                  // hi: first flipped index (sentinel NA)
    #pragma unroll
    for (int it = 0; it < 8; it++) {
        int mid = (lo + hi) >> 1;
        bool sm = (mid < NA) ? (fmaf(yc, cs[mid].y, xc * cs[mid].x) > 0.f) : !s0;
        if (sm == s0) lo = mid; else hi = mid;
    }
    float4 Pj = pre[hi], Pe = pre[NA];
    float b0, b1;
    if (s0) { b0 = Pj.y + (Pe.x - Pj.x); b1 = Pj.w + (Pe.z - Pj.z); }
    else    { b0 = Pj.x + (Pe.y - Pj.y); b1 = Pj.z + (Pe.w - Pj.w); }

    int p = y * NW + x;
    float2 cr = g_corr[p];
    out[p] = fmaxf(b0 + cr.x, 0.f);
    out[NH * NW + p] = fmaxf(b1 + cr.y, 0.f);
}

// ---------------------------------------------------------------------------
extern "C" void kernel_launch(void* const* d_in, const int* in_sizes, int n_in,
                              void* d_out, int out_size) {
    const float* sino = (const float*)d_in[0];
    float* out = (float*)d_out;

    k_filter<<<NB * NA, 256>>>(sino);
    k_strip<<<360, 256>>>();
    k_base<<<(NH * NW) / 256, 256>>>(out);
}